// round 6
// baseline (speedup 1.0000x reference)
#include <cuda_runtime.h>
#include <cuda_bf16.h>
#include <math.h>

#define NN 50000
#define EE 800000
#define ETOT (EE + NN)
#define NEG_SLOPE 0.2f
#define EPS_DEN 1e-16f
#define FULLM 0xffffffffu

typedef unsigned long long ull;

// ---------------- scratch (static __device__, no allocs) ----------------
__device__ float g_h1[NN * 128];      // layer1 projected features [N,4,32]
__device__ float g_asrc1[NN * 4];
__device__ float g_adst1[NN * 4];
__device__ float g_h2[NN * 2];
__device__ float g_asrc2[NN];
__device__ float g_adst2[NN];

__device__ int g_deg[NN];
__device__ int g_rowstart[NN];
__device__ int g_cursor[NN];
__device__ int g_total;
__device__ int g_csrc[ETOT];          // CSR: src node per dst-grouped slot

// ---------------- packed f32x2 helpers (FFMA2 only reachable via PTX) ----------------
__device__ __forceinline__ void ffma2(ull& d, ull a, ull b) {
    asm("fma.rn.f32x2 %0, %1, %2, %3;" : "=l"(d) : "l"(a), "l"(b), "l"(d));
}
__device__ __forceinline__ ull pk2(float lo, float hi) {
    ull r; asm("mov.b64 %0, {%1, %2};" : "=l"(r) : "f"(lo), "f"(hi)); return r;
}
__device__ __forceinline__ float2 upk2(ull v) {
    float lo, hi; asm("mov.b64 {%0, %1}, %2;" : "=f"(lo), "=f"(hi) : "l"(v));
    return make_float2(lo, hi);
}

// ---------------- CSR build ----------------
__global__ void k_initdeg() {
    int n = blockIdx.x * blockDim.x + threadIdx.x;
    if (n < NN) g_deg[n] = 1;          // self loop
    if (n == 0) g_total = 0;
}

// edge_index is int32 on device (JAX x64-disabled demotes int64->int32)
// 4 edges per thread -> 4 independent atomics in flight (hide ATOMG latency)
__global__ void k_count(const int* __restrict__ ei) {
    int t = blockIdx.x * blockDim.x + threadIdx.x;
    if (t >= EE / 4) return;
    int4 d4 = reinterpret_cast<const int4*>(ei + EE)[t];
    atomicAdd(&g_deg[d4.x], 1);
    atomicAdd(&g_deg[d4.y], 1);
    atomicAdd(&g_deg[d4.z], 1);
    atomicAdd(&g_deg[d4.w], 1);
}

// row offsets: intra-block scan + ONE global atomic per block (row order irrelevant)
__global__ __launch_bounds__(256) void k_offsets() {
    __shared__ int wsum[8];
    __shared__ int sbase;
    int t = threadIdx.x;
    int n = blockIdx.x * 256 + t;
    int d = (n < NN) ? g_deg[n] : 0;
    int lane = t & 31, wid = t >> 5;
    int incl = d;
#pragma unroll
    for (int off = 1; off < 32; off <<= 1) {
        int v = __shfl_up_sync(FULLM, incl, off);
        if (lane >= off) incl += v;
    }
    if (lane == 31) wsum[wid] = incl;
    __syncthreads();
    if (t == 0) {
        int run = 0;
#pragma unroll
        for (int w = 0; w < 8; w++) { int v = wsum[w]; wsum[w] = run; run += v; }
        sbase = atomicAdd(&g_total, run);
    }
    __syncthreads();
    if (n < NN) {
        int r = sbase + wsum[wid] + incl - d;
        g_rowstart[n] = r;
        g_cursor[n] = r;
    }
}

// scatter, 4 edges per thread (int4 loads, 4 atomics in flight) + self-loop range
__global__ void k_scatter(const int* __restrict__ ei) {
    int t = blockIdx.x * blockDim.x + threadIdx.x;
    if (t < EE / 4) {
        int4 s4 = reinterpret_cast<const int4*>(ei)[t];
        int4 d4 = reinterpret_cast<const int4*>(ei + EE)[t];
        int p0 = atomicAdd(&g_cursor[d4.x], 1);
        int p1 = atomicAdd(&g_cursor[d4.y], 1);
        int p2 = atomicAdd(&g_cursor[d4.z], 1);
        int p3 = atomicAdd(&g_cursor[d4.w], 1);
        g_csrc[p0] = s4.x;
        g_csrc[p1] = s4.y;
        g_csrc[p2] = s4.z;
        g_csrc[p3] = s4.w;
    } else {
        int n = t - EE / 4;
        if (n < NN) {
            int pos = atomicAdd(&g_cursor[n], 1);
            g_csrc[pos] = n;
        }
    }
}

// ---------------- GEMM1: h1 = x @ W1 + attention scalars (FFMA2) ----------------
#define GEMM1_NPB 64
__global__ __launch_bounds__(128) void k_gemm1(const float* __restrict__ x,
                                               const float* __restrict__ W1,
                                               const float* __restrict__ att_s,
                                               const float* __restrict__ att_d) {
    __shared__ ull xs2[64];
    const int j = threadIdx.x;
    const int lane = j & 31;
    const int head = j >> 5;

    ull wp[64];
#pragma unroll
    for (int k = 0; k < 64; k++)
        wp[k] = pk2(W1[(2 * k) * 128 + j], W1[(2 * k + 1) * 128 + j]);
    const float asj = att_s[j];
    const float adj = att_d[j];

    const int n0 = blockIdx.x * GEMM1_NPB;
#pragma unroll 1
    for (int nn = 0; nn < GEMM1_NPB; nn++) {
        const int n = n0 + nn;
        __syncthreads();
        if (j < 64 && n < NN) xs2[j] = reinterpret_cast<const ull*>(x)[n * 64 + j];
        __syncthreads();
        if (n >= NN) continue;
        ull accA = 0ull, accB = 0ull;   // (0.0f,0.0f) bit pattern
#pragma unroll
        for (int k = 0; k < 32; k++) {
            ffma2(accA, xs2[2 * k], wp[2 * k]);
            ffma2(accB, xs2[2 * k + 1], wp[2 * k + 1]);
        }
        float2 fA = upk2(accA), fB = upk2(accB);
        float acc = (fA.x + fA.y) + (fB.x + fB.y);
        g_h1[n * 128 + j] = acc;
        float ps = acc * asj;
        float pd = acc * adj;
#pragma unroll
        for (int off = 16; off > 0; off >>= 1) {
            ps += __shfl_down_sync(FULLM, ps, off);
            pd += __shfl_down_sync(FULLM, pd, off);
        }
        if (lane == 0) {
            g_asrc1[n * 4 + head] = ps;
            g_adst1[n * 4 + head] = pd;
        }
    }
}

// ---------------- fused layer 1: softmax + aggregate + ELU + W2 proj ----------------
// one warp per destination node; chunks padded to x4 for branch-free unrolled gathers
__global__ __launch_bounds__(256) void k_layer1(const float* __restrict__ b1,
                                                const float* __restrict__ W2,
                                                const float* __restrict__ att_s2,
                                                const float* __restrict__ att_d2) {
    __shared__ int   ssrc[256];
    __shared__ float sex[256 * 4];
    int gt = blockIdx.x * blockDim.x + threadIdx.x;
    int n = gt >> 5;
    if (n >= NN) return;
    const int lane = gt & 31;
    const int head = lane >> 3;
    const int wslot = (threadIdx.x >> 5) * 32;

    const int beg = g_rowstart[n];
    const int end = beg + g_deg[n];
    const float4 adn = reinterpret_cast<const float4*>(g_adst1)[n];
    const ulonglong2* __restrict__ h1v = reinterpret_cast<const ulonglong2*>(g_h1);

    ull acc01 = 0ull, acc23 = 0ull;
    float dx = 0.0f, dy = 0.0f, dz = 0.0f, dw = 0.0f;

    for (int c = beg; c < end; c += 32) {
        const int idx = c + lane;
        const int cnt = min(32, end - c);
        const int cnt4 = (cnt + 3) & ~3;
        __syncwarp(FULLM);
        {
            // all lanes stage; invalid lanes store ex=0 with a safe repeated src
            int s = g_csrc[min(idx, end - 1)];
            float4 as_ = reinterpret_cast<const float4*>(g_asrc1)[s];
            float v0 = as_.x + adn.x, v1 = as_.y + adn.y;
            float v2 = as_.z + adn.z, v3 = as_.w + adn.w;
            v0 = (v0 > 0.0f) ? v0 : NEG_SLOPE * v0;
            v1 = (v1 > 0.0f) ? v1 : NEG_SLOPE * v1;
            v2 = (v2 > 0.0f) ? v2 : NEG_SLOPE * v2;
            v3 = (v3 > 0.0f) ? v3 : NEG_SLOPE * v3;
            float e0 = expf(v0), e1 = expf(v1), e2 = expf(v2), e3 = expf(v3);
            if (idx >= end) { e0 = e1 = e2 = e3 = 0.0f; }
            dx += e0; dy += e1; dz += e2; dw += e3;
            ssrc[wslot + lane] = s;
            float* p = &sex[(wslot + lane) * 4];
            p[0] = e0; p[1] = e1; p[2] = e2; p[3] = e3;
        }
        __syncwarp(FULLM);
        // branch-free gather: 4 edges per iter, 4 LDG.128 in flight
        for (int j = 0; j < cnt4; j += 4) {
            int s0 = ssrc[wslot + j + 0];
            int s1 = ssrc[wslot + j + 1];
            int s2 = ssrc[wslot + j + 2];
            int s3 = ssrc[wslot + j + 3];
            ulonglong2 h0 = h1v[s0 * 32 + lane];
            ulonglong2 h1 = h1v[s1 * 32 + lane];
            ulonglong2 h2 = h1v[s2 * 32 + lane];
            ulonglong2 h3 = h1v[s3 * 32 + lane];
            float ex0 = sex[(wslot + j + 0) * 4 + head];
            float ex1 = sex[(wslot + j + 1) * 4 + head];
            float ex2 = sex[(wslot + j + 2) * 4 + head];
            float ex3 = sex[(wslot + j + 3) * 4 + head];
            ull ee0 = pk2(ex0, ex0), ee1 = pk2(ex1, ex1);
            ull ee2 = pk2(ex2, ex2), ee3 = pk2(ex3, ex3);
            ffma2(acc01, ee0, h0.x); ffma2(acc23, ee0, h0.y);
            ffma2(acc01, ee1, h1.x); ffma2(acc23, ee1, h1.y);
            ffma2(acc01, ee2, h2.x); ffma2(acc23, ee2, h2.y);
            ffma2(acc01, ee3, h3.x); ffma2(acc23, ee3, h3.y);
        }
    }
    // full-warp reduce of the 4 denominators (result in all lanes)
#pragma unroll
    for (int off = 16; off > 0; off >>= 1) {
        dx += __shfl_xor_sync(FULLM, dx, off);
        dy += __shfl_xor_sync(FULLM, dy, off);
        dz += __shfl_xor_sync(FULLM, dz, off);
        dw += __shfl_xor_sync(FULLM, dw, off);
    }
    float denh = (head == 0) ? dx : (head == 1) ? dy : (head == 2) ? dz : dw;
    float r = 1.0f / (denh + EPS_DEN);

    float2 f01 = upk2(acc01), f23 = upk2(acc23);
    float av[4] = {f01.x, f01.y, f23.x, f23.y};
    float p0 = 0.0f, p1 = 0.0f;
#pragma unroll
    for (int m = 0; m < 4; m++) {
        int k = 4 * lane + m;
        float v = av[m] * r + b1[k];
        float ev = (v > 0.0f) ? v : expm1f(v);   // ELU
        p0 = fmaf(ev, W2[k * 2 + 0], p0);
        p1 = fmaf(ev, W2[k * 2 + 1], p1);
    }
#pragma unroll
    for (int off = 16; off > 0; off >>= 1) {
        p0 += __shfl_down_sync(FULLM, p0, off);
        p1 += __shfl_down_sync(FULLM, p1, off);
    }
    if (lane == 0) {
        g_h2[n * 2 + 0] = p0;
        g_h2[n * 2 + 1] = p1;
        g_asrc2[n] = p0 * att_s2[0] + p1 * att_s2[1];
        g_adst2[n] = p0 * att_d2[0] + p1 * att_d2[1];
    }
}

// ---------------- fused layer 2: softmax + aggregate + log_softmax ----------------
// 8 lanes per destination node (avg degree ~17)
__global__ __launch_bounds__(256) void k_layer2(const float* __restrict__ b2,
                                                float* __restrict__ out) {
    int gt = blockIdx.x * blockDim.x + threadIdx.x;
    int n = gt >> 3;
    if (n >= NN) return;
    const int lane = gt & 7;

    const int beg = g_rowstart[n];
    const int end = beg + g_deg[n];
    const float adn = g_adst2[n];

    float den = 0.0f, o0 = 0.0f, o1 = 0.0f;
    for (int idx = beg + lane; idx < end; idx += 8) {
        int s = g_csrc[idx];
        float v = g_asrc2[s] + adn;
        v = (v > 0.0f) ? v : NEG_SLOPE * v;
        float ex = expf(v);
        float2 h = reinterpret_cast<const float2*>(g_h2)[s];
        den += ex;
        o0 = fmaf(ex, h.x, o0);
        o1 = fmaf(ex, h.y, o1);
    }
#pragma unroll
    for (int off = 4; off > 0; off >>= 1) {
        den += __shfl_down_sync(FULLM, den, off, 8);
        o0  += __shfl_down_sync(FULLM, o0, off, 8);
        o1  += __shfl_down_sync(FULLM, o1, off, 8);
    }
    if (lane == 0) {
        float r = 1.0f / (den + EPS_DEN);
        float a = o0 * r + b2[0];
        float b = o1 * r + b2[1];
        float m = fmaxf(a, b);
        float l = m + logf(expf(a - m) + expf(b - m));
        out[n * 2 + 0] = a - l;
        out[n * 2 + 1] = b - l;
    }
}

// ---------------- launch ----------------
extern "C" void kernel_launch(void* const* d_in, const int* in_sizes, int n_in,
                              void* d_out, int out_size) {
    const float* x    = (const float*)d_in[0];
    const int*   ei   = (const int*)d_in[1];
    const float* W1   = (const float*)d_in[2];
    const float* as1  = (const float*)d_in[3];
    const float* ad1  = (const float*)d_in[4];
    const float* b1   = (const float*)d_in[5];
    const float* W2   = (const float*)d_in[6];
    const float* as2  = (const float*)d_in[7];
    const float* ad2  = (const float*)d_in[8];
    const float* b2   = (const float*)d_in[9];
    float* out = (float*)d_out;

    (void)in_sizes; (void)n_in; (void)out_size;

    // one-time side stream + events for capture-legal fork/join
    static cudaStream_t s_side = nullptr;
    static cudaEvent_t  s_evFork = nullptr, s_evJoin = nullptr;
    if (s_side == nullptr) {
        cudaStreamCreateWithFlags(&s_side, cudaStreamNonBlocking);
        cudaEventCreateWithFlags(&s_evFork, cudaEventDisableTiming);
        cudaEventCreateWithFlags(&s_evJoin, cudaEventDisableTiming);
    }

    // fork: CSR build on side stream, gemm1 on main stream (disjoint state)
    cudaEventRecord(s_evFork, 0);
    cudaStreamWaitEvent(s_side, s_evFork, 0);

    k_initdeg<<<(NN + 255) / 256, 256, 0, s_side>>>();
    k_count<<<(EE / 4 + 255) / 256, 256, 0, s_side>>>(ei);
    k_offsets<<<(NN + 255) / 256, 256, 0, s_side>>>();
    k_scatter<<<(EE / 4 + NN + 255) / 256, 256, 0, s_side>>>(ei);
    cudaEventRecord(s_evJoin, s_side);

    k_gemm1<<<(NN + GEMM1_NPB - 1) / GEMM1_NPB, 128>>>(x, W1, as1, ad1);

    // join: layer kernels need both CSR and gemm outputs
    cudaStreamWaitEvent(0, s_evJoin, 0);

    {
        long long tot = (long long)NN * 32;
        k_layer1<<<(int)((tot + 255) / 256), 256>>>(b1, W2, as2, ad2);
    }
    {
        long long tot = (long long)NN * 8;
        k_layer2<<<(int)((tot + 255) / 256), 256>>>(b2, out);
    }
}

// round 7
// speedup vs baseline: 1.0816x; 1.0816x over previous
#include <cuda_runtime.h>
#include <cuda_fp16.h>
#include <math.h>

#define NN 50000
#define EE 800000
#define ETOT (EE + NN)
#define NEG_SLOPE 0.2f
#define EPS_DEN 1e-16f
#define FULLM 0xffffffffu

typedef unsigned long long ull;

// ---------------- scratch (static __device__, no allocs) ----------------
__device__ uint2 g_h1[NN * 32];       // layer1 features, fp16: 128 halves/node (4 per lane)
__device__ float g_asrc1[NN * 4];
__device__ float g_adst1[NN * 4];
__device__ float g_h2[NN * 2];
__device__ float g_asrc2[NN];
__device__ float g_adst2[NN];

__device__ int g_deg[NN];             // after k_offsets: includes self-loop
__device__ int g_rowstart[NN];
__device__ int g_cursor[NN];
__device__ int g_total;
__device__ int g_csrc[ETOT];          // CSR: src node per dst-grouped slot

// ---------------- packed f32x2 helpers (FFMA2 only reachable via PTX) ----------------
__device__ __forceinline__ void ffma2(ull& d, ull a, ull b) {
    asm("fma.rn.f32x2 %0, %1, %2, %3;" : "=l"(d) : "l"(a), "l"(b), "l"(d));
}
__device__ __forceinline__ ull pk2(float lo, float hi) {
    ull r; asm("mov.b64 %0, {%1, %2};" : "=l"(r) : "f"(lo), "f"(hi)); return r;
}
__device__ __forceinline__ float2 upk2(ull v) {
    float lo, hi; asm("mov.b64 {%0, %1}, %2;" : "=f"(lo), "=f"(hi) : "l"(v));
    return make_float2(lo, hi);
}

// ---------------- CSR build ----------------
// edge_index is int32 on device (JAX x64-disabled demotes int64->int32)
// 8 edges per thread -> 8 independent REDs in flight
__global__ void k_count(const int* __restrict__ ei) {
    int t = blockIdx.x * blockDim.x + threadIdx.x;
    if (t >= EE / 8) return;
    int4 a = reinterpret_cast<const int4*>(ei + EE)[2 * t];
    int4 b = reinterpret_cast<const int4*>(ei + EE)[2 * t + 1];
    atomicAdd(&g_deg[a.x], 1); atomicAdd(&g_deg[a.y], 1);
    atomicAdd(&g_deg[a.z], 1); atomicAdd(&g_deg[a.w], 1);
    atomicAdd(&g_deg[b.x], 1); atomicAdd(&g_deg[b.y], 1);
    atomicAdd(&g_deg[b.z], 1); atomicAdd(&g_deg[b.w], 1);
}

// row offsets: intra-block scan + ONE global atomic per block (row order irrelevant);
// also folds the +1 self-loop into g_deg.
__global__ __launch_bounds__(256) void k_offsets() {
    __shared__ int wsum[8];
    __shared__ int sbase;
    int t = threadIdx.x;
    int n = blockIdx.x * 256 + t;
    int d = (n < NN) ? (g_deg[n] + 1) : 0;   // +1 self loop
    int lane = t & 31, wid = t >> 5;
    int incl = d;
#pragma unroll
    for (int off = 1; off < 32; off <<= 1) {
        int v = __shfl_up_sync(FULLM, incl, off);
        if (lane >= off) incl += v;
    }
    if (lane == 31) wsum[wid] = incl;
    __syncthreads();
    if (t == 0) {
        int run = 0;
#pragma unroll
        for (int w = 0; w < 8; w++) { int v = wsum[w]; wsum[w] = run; run += v; }
        sbase = atomicAdd(&g_total, run);
    }
    __syncthreads();
    if (n < NN) {
        int r = sbase + wsum[wid] + incl - d;
        g_deg[n] = d;            // now includes self loop
        g_rowstart[n] = r;
        g_cursor[n] = r;
    }
}

// scatter, 8 edges per thread (8 atomics in flight) + self-loop tail
__global__ void k_scatter(const int* __restrict__ ei) {
    int t = blockIdx.x * blockDim.x + threadIdx.x;
    if (t < EE / 8) {
        int4 sa = reinterpret_cast<const int4*>(ei)[2 * t];
        int4 sb = reinterpret_cast<const int4*>(ei)[2 * t + 1];
        int4 da = reinterpret_cast<const int4*>(ei + EE)[2 * t];
        int4 db = reinterpret_cast<const int4*>(ei + EE)[2 * t + 1];
        int p0 = atomicAdd(&g_cursor[da.x], 1);
        int p1 = atomicAdd(&g_cursor[da.y], 1);
        int p2 = atomicAdd(&g_cursor[da.z], 1);
        int p3 = atomicAdd(&g_cursor[da.w], 1);
        int p4 = atomicAdd(&g_cursor[db.x], 1);
        int p5 = atomicAdd(&g_cursor[db.y], 1);
        int p6 = atomicAdd(&g_cursor[db.z], 1);
        int p7 = atomicAdd(&g_cursor[db.w], 1);
        g_csrc[p0] = sa.x; g_csrc[p1] = sa.y; g_csrc[p2] = sa.z; g_csrc[p3] = sa.w;
        g_csrc[p4] = sb.x; g_csrc[p5] = sb.y; g_csrc[p6] = sb.z; g_csrc[p7] = sb.w;
    } else {
        int n = t - EE / 8;
        if (n < NN) {
            int pos = atomicAdd(&g_cursor[n], 1);
            g_csrc[pos] = n;
        }
    }
}

// ---------------- GEMM1: h1 = x @ W1 + attention scalars (FFMA2, fp16 h1 out) ----------------
#define GEMM1_NPB 64
__global__ __launch_bounds__(128) void k_gemm1(const float* __restrict__ x,
                                               const float* __restrict__ W1,
                                               const float* __restrict__ att_s,
                                               const float* __restrict__ att_d) {
    __shared__ ulonglong2 xs4[32];    // one x row as 32 x 16B
    const int j = threadIdx.x;
    const int lane = j & 31;
    const int head = j >> 5;

    ull wp[64];
#pragma unroll
    for (int k = 0; k < 64; k++)
        wp[k] = pk2(W1[(2 * k) * 128 + j], W1[(2 * k + 1) * 128 + j]);
    const float asj = att_s[j];
    const float adj = att_d[j];

    const int n0 = blockIdx.x * GEMM1_NPB;
#pragma unroll 1
    for (int nn = 0; nn < GEMM1_NPB; nn++) {
        const int n = n0 + nn;
        __syncthreads();
        if (j < 32 && n < NN) xs4[j] = reinterpret_cast<const ulonglong2*>(x)[n * 32 + j];
        __syncthreads();
        if (n >= NN) continue;
        ull accA = 0ull, accB = 0ull;
#pragma unroll
        for (int k = 0; k < 32; k++) {
            ulonglong2 v = xs4[k];
            ffma2(accA, v.x, wp[2 * k]);
            ffma2(accB, v.y, wp[2 * k + 1]);
        }
        float2 fA = upk2(accA), fB = upk2(accB);
        float acc = (fA.x + fA.y) + (fB.x + fB.y);
        // pack adjacent columns into half2 (even thread stores pair)
        float accR = __shfl_down_sync(FULLM, acc, 1);
        if ((j & 1) == 0)
            reinterpret_cast<__half2*>(g_h1)[n * 64 + (j >> 1)] = __floats2half2_rn(acc, accR);
        float ps = acc * asj;
        float pd = acc * adj;
#pragma unroll
        for (int off = 16; off > 0; off >>= 1) {
            ps += __shfl_down_sync(FULLM, ps, off);
            pd += __shfl_down_sync(FULLM, pd, off);
        }
        if (lane == 0) {
            g_asrc1[n * 4 + head] = ps;
            g_adst1[n * 4 + head] = pd;
        }
    }
}

// ---------------- fused layer 1: softmax + aggregate + ELU + W2 proj ----------------
// one warp per destination node; fp16 h1 gathers (8B/lane/edge), unroll-8
__global__ __launch_bounds__(256) void k_layer1(const float* __restrict__ b1,
                                                const float* __restrict__ W2,
                                                const float* __restrict__ att_s2,
                                                const float* __restrict__ att_d2) {
    __shared__ int   ssrc[256];
    __shared__ float sex[256 * 4];
    int gt = blockIdx.x * blockDim.x + threadIdx.x;
    int n = gt >> 5;
    if (n >= NN) return;
    const int lane = gt & 31;
    const int head = lane >> 3;
    const int wslot = (threadIdx.x >> 5) * 32;

    const int beg = g_rowstart[n];
    const int end = beg + g_deg[n];
    const float4 adn = reinterpret_cast<const float4*>(g_adst1)[n];
    const uint2* __restrict__ h1v = g_h1;

    float acc0 = 0.0f, acc1 = 0.0f, acc2 = 0.0f, acc3 = 0.0f;
    float dx = 0.0f, dy = 0.0f, dz = 0.0f, dw = 0.0f;

    for (int c = beg; c < end; c += 32) {
        const int idx = c + lane;
        const int cnt = min(32, end - c);
        const int cnt8 = (cnt + 7) & ~7;
        __syncwarp(FULLM);
        {
            int s = g_csrc[min(idx, end - 1)];
            float4 as_ = reinterpret_cast<const float4*>(g_asrc1)[s];
            float v0 = as_.x + adn.x, v1 = as_.y + adn.y;
            float v2 = as_.z + adn.z, v3 = as_.w + adn.w;
            v0 = (v0 > 0.0f) ? v0 : NEG_SLOPE * v0;
            v1 = (v1 > 0.0f) ? v1 : NEG_SLOPE * v1;
            v2 = (v2 > 0.0f) ? v2 : NEG_SLOPE * v2;
            v3 = (v3 > 0.0f) ? v3 : NEG_SLOPE * v3;
            float e0 = expf(v0), e1 = expf(v1), e2 = expf(v2), e3 = expf(v3);
            if (idx >= end) { e0 = e1 = e2 = e3 = 0.0f; }
            dx += e0; dy += e1; dz += e2; dw += e3;
            ssrc[wslot + lane] = s;
            float* p = &sex[(wslot + lane) * 4];
            p[0] = e0; p[1] = e1; p[2] = e2; p[3] = e3;
        }
        __syncwarp(FULLM);
        // branch-free gather: 8 edges per iter, 8 LDG.64 in flight
        for (int j = 0; j < cnt8; j += 8) {
            uint2 u[8];
#pragma unroll
            for (int i = 0; i < 8; i++) {
                int s = ssrc[wslot + j + i];
                u[i] = h1v[s * 32 + lane];
            }
#pragma unroll
            for (int i = 0; i < 8; i++) {
                float ex = sex[(wslot + j + i) * 4 + head];
                float2 a = __half22float2(*reinterpret_cast<__half2*>(&u[i].x));
                float2 b = __half22float2(*reinterpret_cast<__half2*>(&u[i].y));
                acc0 = fmaf(ex, a.x, acc0);
                acc1 = fmaf(ex, a.y, acc1);
                acc2 = fmaf(ex, b.x, acc2);
                acc3 = fmaf(ex, b.y, acc3);
            }
        }
    }
    // full-warp reduce of the 4 denominators (result in all lanes)
#pragma unroll
    for (int off = 16; off > 0; off >>= 1) {
        dx += __shfl_xor_sync(FULLM, dx, off);
        dy += __shfl_xor_sync(FULLM, dy, off);
        dz += __shfl_xor_sync(FULLM, dz, off);
        dw += __shfl_xor_sync(FULLM, dw, off);
    }
    float denh = (head == 0) ? dx : (head == 1) ? dy : (head == 2) ? dz : dw;
    float r = 1.0f / (denh + EPS_DEN);

    float av[4] = {acc0, acc1, acc2, acc3};
    float p0 = 0.0f, p1 = 0.0f;
#pragma unroll
    for (int m = 0; m < 4; m++) {
        int k = 4 * lane + m;
        float v = av[m] * r + b1[k];
        float ev = (v > 0.0f) ? v : expm1f(v);   // ELU
        p0 = fmaf(ev, W2[k * 2 + 0], p0);
        p1 = fmaf(ev, W2[k * 2 + 1], p1);
    }
#pragma unroll
    for (int off = 16; off > 0; off >>= 1) {
        p0 += __shfl_down_sync(FULLM, p0, off);
        p1 += __shfl_down_sync(FULLM, p1, off);
    }
    if (lane == 0) {
        g_h2[n * 2 + 0] = p0;
        g_h2[n * 2 + 1] = p1;
        g_asrc2[n] = p0 * att_s2[0] + p1 * att_s2[1];
        g_adst2[n] = p0 * att_d2[0] + p1 * att_d2[1];
    }
}

// ---------------- fused layer 2: softmax + aggregate + log_softmax ----------------
// 8 lanes per destination node (avg degree ~17)
__global__ __launch_bounds__(256) void k_layer2(const float* __restrict__ b2,
                                                float* __restrict__ out) {
    int gt = blockIdx.x * blockDim.x + threadIdx.x;
    int n = gt >> 3;
    if (n >= NN) return;
    const int lane = gt & 7;

    const int beg = g_rowstart[n];
    const int end = beg + g_deg[n];
    const float adn = g_adst2[n];

    float den = 0.0f, o0 = 0.0f, o1 = 0.0f;
    for (int idx = beg + lane; idx < end; idx += 8) {
        int s = g_csrc[idx];
        float v = g_asrc2[s] + adn;
        v = (v > 0.0f) ? v : NEG_SLOPE * v;
        float ex = expf(v);
        float2 h = reinterpret_cast<const float2*>(g_h2)[s];
        den += ex;
        o0 = fmaf(ex, h.x, o0);
        o1 = fmaf(ex, h.y, o1);
    }
#pragma unroll
    for (int off = 4; off > 0; off >>= 1) {
        den += __shfl_down_sync(FULLM, den, off, 8);
        o0  += __shfl_down_sync(FULLM, o0, off, 8);
        o1  += __shfl_down_sync(FULLM, o1, off, 8);
    }
    if (lane == 0) {
        float r = 1.0f / (den + EPS_DEN);
        float a = o0 * r + b2[0];
        float b = o1 * r + b2[1];
        float m = fmaxf(a, b);
        float l = m + logf(expf(a - m) + expf(b - m));
        out[n * 2 + 0] = a - l;
        out[n * 2 + 1] = b - l;
    }
}

// ---------------- launch ----------------
extern "C" void kernel_launch(void* const* d_in, const int* in_sizes, int n_in,
                              void* d_out, int out_size) {
    const float* x    = (const float*)d_in[0];
    const int*   ei   = (const int*)d_in[1];
    const float* W1   = (const float*)d_in[2];
    const float* as1  = (const float*)d_in[3];
    const float* ad1  = (const float*)d_in[4];
    const float* b1   = (const float*)d_in[5];
    const float* W2   = (const float*)d_in[6];
    const float* as2  = (const float*)d_in[7];
    const float* ad2  = (const float*)d_in[8];
    const float* b2   = (const float*)d_in[9];
    float* out = (float*)d_out;

    (void)in_sizes; (void)n_in; (void)out_size;

    // one-time handles (API objects, not cached results)
    static cudaStream_t s_side = nullptr;
    static cudaEvent_t  s_evFork = nullptr, s_evJoin = nullptr;
    static void *p_deg = nullptr, *p_total = nullptr;
    if (s_side == nullptr) {
        cudaStreamCreateWithFlags(&s_side, cudaStreamNonBlocking);
        cudaEventCreateWithFlags(&s_evFork, cudaEventDisableTiming);
        cudaEventCreateWithFlags(&s_evJoin, cudaEventDisableTiming);
        cudaGetSymbolAddress(&p_deg, g_deg);
        cudaGetSymbolAddress(&p_total, g_total);
    }

    // fork: CSR build on side stream, gemm1 on main stream (disjoint state)
    cudaEventRecord(s_evFork, 0);
    cudaStreamWaitEvent(s_side, s_evFork, 0);

    cudaMemsetAsync(p_deg, 0, NN * sizeof(int), s_side);
    cudaMemsetAsync(p_total, 0, sizeof(int), s_side);
    k_count<<<(EE / 8 + 255) / 256, 256, 0, s_side>>>(ei);
    k_offsets<<<(NN + 255) / 256, 256, 0, s_side>>>();
    k_scatter<<<(EE / 8 + NN + 255) / 256, 256, 0, s_side>>>(ei);
    cudaEventRecord(s_evJoin, s_side);

    k_gemm1<<<(NN + GEMM1_NPB - 1) / GEMM1_NPB, 128>>>(x, W1, as1, ad1);

    // join: layer kernels need both CSR and gemm outputs
    cudaStreamWaitEvent(0, s_evJoin, 0);

    {
        long long tot = (long long)NN * 32;
        k_layer1<<<(int)((tot + 255) / 256), 256>>>(b1, W2, as2, ad2);
    }
    {
        long long tot = (long long)NN * 8;
        k_layer2<<<(int)((tot + 255) / 256), 256>>>(b2, out);
    }
}